// round 3
// baseline (speedup 1.0000x reference)
#include <cuda_runtime.h>
#include <cstdint>
#include <cstddef>

// ---------------------------------------------------------------------------
// Problem constants
// ---------------------------------------------------------------------------
#define JAX_PARTITIONABLE 1   // modern JAX default (threefry_partitionable=True)

constexpr int ND  = 10000;    // N_DRUGS
constexpr int NT  = 20000;    // N_TAILS (unused directly)
constexpr int NR  = 100;      // N_RELS  (unused directly)
constexpr int E   = 1000000;
constexpr int DIM = 64;
constexpr int S   = 16;       // SAMPLE_SIZE
constexpr int CAP = 512;      // per-node bucket capacity (max deg ~160 for this input)

// ---------------------------------------------------------------------------
// Static device scratch (no runtime allocation allowed)
// ---------------------------------------------------------------------------
__device__ unsigned long long g_bucket[(size_t)ND * CAP];  // (m<<20)|edge_idx keys
__device__ int   g_cnt[ND];          // per-node degree (bucket cursor)
__device__ int   g_sel[ND * S];      // per-node selected edge ids, by rank
__device__ int   g_nsel[ND];         // min(deg, S)
__device__ float g_neigh[ND * DIM];
__device__ float g_y[ND * DIM];
__device__ float g_colsum[DIM];
__device__ float g_colsumsq[DIM];
__device__ float g_w2r[DIM];         // rowsum of W2
__device__ float g_b2sum;
__device__ float g_mean[DIM];
__device__ float g_inv[DIM];

// ---------------------------------------------------------------------------
// Threefry2x32 (bit-exact JAX replica)
// ---------------------------------------------------------------------------
__device__ __forceinline__ uint32_t rotl32(uint32_t v, int r) {
    return (v << r) | (v >> (32 - r));
}

__device__ __forceinline__ void tf2x32(uint32_t k0, uint32_t k1,
                                       uint32_t x0, uint32_t x1,
                                       uint32_t& o0, uint32_t& o1)
{
    uint32_t k2 = k0 ^ k1 ^ 0x1BD11BDAu;
    x0 += k0; x1 += k1;
#define TF_R4(a,b,c,d)                                   \
    x0 += x1; x1 = rotl32(x1,a); x1 ^= x0;               \
    x0 += x1; x1 = rotl32(x1,b); x1 ^= x0;               \
    x0 += x1; x1 = rotl32(x1,c); x1 ^= x0;               \
    x0 += x1; x1 = rotl32(x1,d); x1 ^= x0;
    TF_R4(13,15,26,6);   x0 += k1; x1 += k2 + 1u;
    TF_R4(17,29,16,24);  x0 += k2; x1 += k0 + 2u;
    TF_R4(13,15,26,6);   x0 += k0; x1 += k1 + 3u;
    TF_R4(17,29,16,24);  x0 += k1; x1 += k2 + 4u;
    TF_R4(13,15,26,6);   x0 += k2; x1 += k0 + 5u;
#undef TF_R4
    o0 = x0; o1 = x1;
}

// key(42) -> split -> (k1, k2). Base key is (0, 42).
__device__ __forceinline__ void derive_k1(uint32_t& a, uint32_t& b) {
#if JAX_PARTITIONABLE
    tf2x32(0u, 42u, 0u, 0u, a, b);            // key_0 = block(key, (0,0))
#else
    uint32_t a0,b0,a1,b1;
    tf2x32(0u, 42u, 0u, 2u, a0, b0);          // counts iota(4) split as [0,1],[2,3]
    tf2x32(0u, 42u, 1u, 3u, a1, b1);
    a = a0; b = a1;                           // key_0 = (out0 of both blocks)
#endif
}

__device__ __forceinline__ void derive_k2(uint32_t& a, uint32_t& b) {
#if JAX_PARTITIONABLE
    tf2x32(0u, 42u, 0u, 1u, a, b);            // key_1 = block(key, (0,1))
#else
    uint32_t a0,b0,a1,b1;
    tf2x32(0u, 42u, 0u, 2u, a0, b0);
    tf2x32(0u, 42u, 1u, 3u, a1, b1);
    a = b0; b = b1;                           // key_1 = (out1 of both blocks)
#endif
}

// i-th 32-bit random word of random_bits(key, 32, (n,))
__device__ __forceinline__ uint32_t jax_bits32(uint32_t ka, uint32_t kb,
                                               uint32_t i, uint32_t n)
{
#if JAX_PARTITIONABLE
    uint32_t o0, o1;
    tf2x32(ka, kb, 0u, i, o0, o1);
    return o0 ^ o1;                           // 32-bit fold of the 2x32 block
#else
    uint32_t half = n >> 1;                   // n even for all our uses
    uint32_t j = (i < half) ? i : (i - half);
    uint32_t o0, o1;
    tf2x32(ka, kb, j, j + half, o0, o1);
    return (i < half) ? o0 : o1;
#endif
}

// ---------------------------------------------------------------------------
// K0: zero counters, precompute w2 rowsums / b2 sum
// ---------------------------------------------------------------------------
__global__ void k_init(const float* __restrict__ W2, const float* __restrict__ b2)
{
    int t = blockIdx.x * blockDim.x + threadIdx.x;
    if (t < ND) g_cnt[t] = 0;
    if (t < DIM) {
        g_colsum[t]   = 0.f;
        g_colsumsq[t] = 0.f;
        float s = 0.f;
        #pragma unroll 8
        for (int k = 0; k < DIM; k++) s += W2[t * DIM + k];
        g_w2r[t] = s;
    }
    if (t == 0) {
        float s = 0.f;
        #pragma unroll 8
        for (int k = 0; k < DIM; k++) s += b2[k];
        g_b2sum = s;
    }
}

// ---------------------------------------------------------------------------
// K1: per-edge uniform r, scatter (m<<20 | edge_idx) into per-node buckets
// ---------------------------------------------------------------------------
__global__ void k_scatter(const int* __restrict__ DKG)
{
    int i = blockIdx.x * blockDim.x + threadIdx.x;
    if (i >= E) return;
    uint32_t ka, kb;
    derive_k1(ka, kb);                        // constant-folds
    uint32_t bits = jax_bits32(ka, kb, (uint32_t)i, (uint32_t)E);
    uint32_t m = bits >> 9;                   // r = m * 2^-23 exactly; order by m
    int head = DKG[3 * i];
    int c = atomicAdd(&g_cnt[head], 1);
    if (c < CAP)
        g_bucket[(size_t)head * CAP + c] =
            (((unsigned long long)m) << 20) | (unsigned long long)(uint32_t)i;
}

// ---------------------------------------------------------------------------
// K2: per-node exact rank-by-count; keep ranks < S (stable lexsort semantics)
// ---------------------------------------------------------------------------
__global__ __launch_bounds__(128) void k_select()
{
    __shared__ unsigned long long sk[CAP];
    int d = blockIdx.x;
    int deg = g_cnt[d];
    if (deg > CAP) deg = CAP;                 // never triggers for this input
    for (int i = threadIdx.x; i < deg; i += blockDim.x)
        sk[i] = g_bucket[(size_t)d * CAP + i];
    __syncthreads();
    for (int i = threadIdx.x; i < deg; i += blockDim.x) {
        unsigned long long key = sk[i];
        int r = 0;
        for (int j = 0; j < deg; j++) r += (sk[j] < key);   // keys unique (idx in low bits)
        if (r < S) g_sel[d * S + r] = (int)(key & 0xFFFFFull);
    }
    if (threadIdx.x == 0) g_nsel[d] = (deg < S) ? deg : S;
}

// ---------------------------------------------------------------------------
// K3: per-node MLP scores on the <=16 selected edges + neighbor aggregation.
//     score(e) = sigmoid(h0 @ W1 + b1) . w2row + sum(b2),
//     h0 = drug_emb[d] * rel_emb[rel_e];  neigh[d] += score * tail_emb[tail_e]
// ---------------------------------------------------------------------------
__global__ __launch_bounds__(128) void k_node(
    const int*   __restrict__ DKG,
    const float* __restrict__ drug,
    const float* __restrict__ rel_emb,
    const float* __restrict__ tail_emb,
    const float* __restrict__ W1,
    const float* __restrict__ b1)
{
    __shared__ float W1s[DIM * DIM];          // 16 KB
    __shared__ float b1s[DIM], w2s[DIM], de[DIM];
    __shared__ float H0[4][4][DIM];           // [warp][edge][j]
    __shared__ int   elist[S];
    __shared__ float pacc[4][DIM];

    int d    = blockIdx.x;
    int tid  = threadIdx.x;
    int warp = tid >> 5, lane = tid & 31;

    for (int i = tid; i < DIM * DIM; i += 128) W1s[i] = W1[i];
    if (tid < DIM) {
        b1s[tid] = b1[tid];
        w2s[tid] = g_w2r[tid];
        de[tid]  = drug[d * DIM + tid];
    }
    if (tid < S) {
        int s = tid;
        int n   = g_nsel[d];
        int deg = g_cnt[d]; if (deg > CAP) deg = CAP;
        int e = -1;
        if (s < n) {
            e = g_sel[d * S + s];
        } else if (deg > 0) {
            // deg < S path: extra draws WITH replacement (dead for this input)
            int t = s - n;
            uint32_t ka, kb; derive_k2(ka, kb);
            uint32_t idx = (uint32_t)(d * S + t);
            uint32_t hi = jax_bits32(ka, kb, idx,            2u * ND * S);
            uint32_t lo = jax_bits32(ka, kb, idx + ND * S,   2u * ND * S);
            const uint32_t span = 2147483647u;
            uint32_t mult = (65536u * 65536u) % span;        // uint32 wrap, as in lax
            uint32_t off  = ((hi % span) * mult + (lo % span)) % span;
            e = g_sel[d * S + (int)(off % (uint32_t)deg)];
        }
        elist[s] = e;
    }
    __syncthreads();

    // each warp processes 4 edge slots: s = warp*4 + q
    int  eids[4]; bool valid[4];
    #pragma unroll
    for (int q = 0; q < 4; q++) {
        int e = elist[warp * 4 + q];
        valid[q] = (e >= 0);
        eids[q]  = (e >= 0) ? e : 0;
    }
    #pragma unroll
    for (int q = 0; q < 4; q++) {
        int r = DKG[3 * eids[q] + 2];
        H0[warp][q][lane]      = de[lane]      * rel_emb[r * DIM + lane];
        H0[warp][q][lane + 32] = de[lane + 32] * rel_emb[r * DIM + lane + 32];
    }
    __syncwarp();

    float y[4][2];
    #pragma unroll
    for (int q = 0; q < 4; q++) { y[q][0] = b1s[lane]; y[q][1] = b1s[lane + 32]; }

    #pragma unroll
    for (int j = 0; j < DIM; j++) {
        float w0 = W1s[j * DIM + lane];
        float w1 = W1s[j * DIM + lane + 32];
        #pragma unroll
        for (int q = 0; q < 4; q++) {
            float h = H0[warp][q][j];
            y[q][0] += h * w0;
            y[q][1] += h * w1;
        }
    }

    float b2s = g_b2sum;
    float p0 = 0.f, p1 = 0.f;
    #pragma unroll
    for (int q = 0; q < 4; q++) {
        float s0 = w2s[lane]      / (1.f + __expf(-y[q][0]));
        float s1 = w2s[lane + 32] / (1.f + __expf(-y[q][1]));
        float v = s0 + s1;
        #pragma unroll
        for (int o = 16; o; o >>= 1) v += __shfl_xor_sync(0xFFFFFFFFu, v, o);
        float score = v + b2s;
        if (valid[q]) {
            int t = DKG[3 * eids[q] + 1];
            p0 += score * tail_emb[t * DIM + lane];
            p1 += score * tail_emb[t * DIM + lane + 32];
        }
    }
    pacc[warp][lane]      = p0;
    pacc[warp][lane + 32] = p1;
    __syncthreads();
    if (tid < DIM) {
        float s = pacc[0][tid] + pacc[1][tid] + pacc[2][tid] + pacc[3][tid];
        g_neigh[d * DIM + tid] = s;
    }
}

// ---------------------------------------------------------------------------
// K4: y = [drug | neigh] @ Wc + bc, plus column sum / sumsq partials
// ---------------------------------------------------------------------------
__global__ __launch_bounds__(256) void k_gemm(
    const float* __restrict__ drug,
    const float* __restrict__ Wc,
    const float* __restrict__ bc)
{
    __shared__ float Wcs[2 * DIM * DIM];      // 32 KB
    __shared__ float rsum[4][DIM], rsq[4][DIM];
    int tid = threadIdx.x;
    int k   = tid & 63;
    int ty  = tid >> 6;
    for (int i = tid; i < 2 * DIM * DIM; i += 256) Wcs[i] = Wc[i];
    __syncthreads();

    float ls = 0.f, lq = 0.f;
    int r0 = blockIdx.x * 16;
    for (int it = 0; it < 4; it++) {
        int r = r0 + it * 4 + ty;
        if (r < ND) {
            float acc = bc[k];
            #pragma unroll 8
            for (int j = 0; j < DIM; j++) acc += drug[r * DIM + j] * Wcs[j * DIM + k];
            #pragma unroll 8
            for (int j = 0; j < DIM; j++) acc += g_neigh[r * DIM + j] * Wcs[(DIM + j) * DIM + k];
            g_y[r * DIM + k] = acc;
            ls += acc; lq += acc * acc;
        }
    }
    rsum[ty][k] = ls; rsq[ty][k] = lq;
    __syncthreads();
    if (ty == 0) {
        float s = rsum[0][k] + rsum[1][k] + rsum[2][k] + rsum[3][k];
        float q = rsq[0][k]  + rsq[1][k]  + rsq[2][k]  + rsq[3][k];
        atomicAdd(&g_colsum[k],   s);
        atomicAdd(&g_colsumsq[k], q);
    }
}

// ---------------------------------------------------------------------------
// K5: batchnorm stats
// ---------------------------------------------------------------------------
__global__ void k_stats()
{
    int k = threadIdx.x;
    float mean = g_colsum[k] / (float)ND;
    float var  = g_colsumsq[k] / (float)ND - mean * mean;
    g_mean[k] = mean;
    g_inv[k]  = rsqrtf(var + 1e-5f);
}

// ---------------------------------------------------------------------------
// K6: normalized output
// ---------------------------------------------------------------------------
__global__ void k_out(const float* __restrict__ gamma,
                      const float* __restrict__ beta,
                      float* __restrict__ out)
{
    int i = blockIdx.x * blockDim.x + threadIdx.x;
    if (i < ND * DIM) {
        int k = i & 63;
        out[i] = gamma[k] * (g_y[i] - g_mean[k]) * g_inv[k] + beta[k];
    }
}

// ---------------------------------------------------------------------------
// Entry point. Output tuple layout: [HFEmbeding (10000x64) | out (10000x64) | X (10000)]
// ---------------------------------------------------------------------------
extern "C" void kernel_launch(void* const* d_in, const int* in_sizes, int n_in,
                              void* d_out, int out_size)
{
    const float* HF    = (const float*)d_in[0];
    const float* X     = (const float*)d_in[1];
    const float* drug  = (const float*)d_in[2];
    const float* rel   = (const float*)d_in[3];
    const float* tail  = (const float*)d_in[4];
    const float* W1    = (const float*)d_in[5];
    const float* b1    = (const float*)d_in[6];
    const float* W2    = (const float*)d_in[7];
    const float* b2    = (const float*)d_in[8];
    const float* Wc    = (const float*)d_in[9];
    const float* bc    = (const float*)d_in[10];
    const float* gamma = (const float*)d_in[11];
    const float* beta  = (const float*)d_in[12];
    const int*   DKG   = (const int*)d_in[13];
    float* out = (float*)d_out;

    k_init   <<<(ND + 255) / 256, 256>>>(W2, b2);
    k_scatter<<<(E + 255) / 256, 256>>>(DKG);
    k_select <<<ND, 128>>>();
    k_node   <<<ND, 128>>>(DKG, drug, rel, tail, W1, b1);
    k_gemm   <<<(ND + 15) / 16, 256>>>(drug, Wc, bc);
    k_stats  <<<1, DIM>>>();
    k_out    <<<(ND * DIM + 255) / 256, 256>>>(gamma, beta, out + ND * DIM);

    cudaMemcpyAsync(out,               HF, (size_t)ND * DIM * sizeof(float),
                    cudaMemcpyDeviceToDevice);
    cudaMemcpyAsync(out + 2 * ND * DIM, X, (size_t)ND * sizeof(float),
                    cudaMemcpyDeviceToDevice);
}